// round 8
// baseline (speedup 1.0000x reference)
#include <cuda_runtime.h>
#include <cstdint>
#include <cstddef>

#define B_  2048
#define T_  256
#define D_  42
#define H_  64

typedef unsigned long long ull;

// 512MB scratch: gate-packed layer-0 preactivations, {(i,f),(g,o)} per (t,b,j)
__device__ ulonglong2 g_gx0[(size_t)B_ * T_ * H_];

// ---------------------------------------------------------------- helpers ---
__device__ __forceinline__ void fma2(ull& d, ull a, ull b) {
    // packed fp32x2 FMA: d = a*b + d  (two IEEE fp32 MACs per instruction)
    asm("fma.rn.f32x2 %0, %1, %2, %0;" : "+l"(d) : "l"(a), "l"(b));
}
__device__ __forceinline__ ull dupf(float v) {
    unsigned r = __float_as_uint(v);
    ull d; asm("mov.b64 %0, {%1, %1};" : "=l"(d) : "r"(r));
    return d;
}
__device__ __forceinline__ ull dup2(float v) {
    ull u = (ull)__float_as_uint(v); return u | (u << 32);
}
__device__ __forceinline__ ull pack2(float lo, float hi) {
    return (ull)__float_as_uint(lo) | ((ull)__float_as_uint(hi) << 32);
}
__device__ __forceinline__ float lo32(ull u) { return __uint_as_float((unsigned)u); }
__device__ __forceinline__ float hi32(ull u) { return __uint_as_float((unsigned)(u >> 32)); }
__device__ __forceinline__ float sigf(float x)   { return __fdividef(1.0f, 1.0f + __expf(-x)); }
__device__ __forceinline__ float tanhf_(float x) { float e = __expf(2.0f * x); return 1.0f - __fdividef(2.0f, e + 1.0f); }

// ============================================================================
// Prepass: gx0[t][b][j] = x[b,t,:] . W_ih0^T + b_ih0 + b_hh0   (gate-packed)
// 32 (b,t) rows per block; thread (j = tid&63, slot = tid>>6) does 8 rows.
// ============================================================================
#define PPX      34                             // x-dup pitch in ulls (even)
#define PP_SMEM  (D_ * H_ * 16 + D_ * PPX * 8)  // 43008 + 11424 = 54432 B

__global__ void __launch_bounds__(256, 2)
gx0_prepass(const float* __restrict__ x,
            const float* __restrict__ Wih0,
            const float* __restrict__ bih0,
            const float* __restrict__ bhh0)
{
    extern __shared__ char sm[];
    ulonglong2* Wp = (ulonglong2*)sm;            // [d*64 + j] {(i,f),(g,o)}
    ull*        xd = (ull*)(sm + D_ * H_ * 16);  // [d*PPX + row] duplicated x

    const int tid  = threadIdx.x;
    const int j    = tid & 63;
    const int slot = tid >> 6;                   // 0..3
    const int r0   = slot * 8;                   // first of this thread's 8 rows
    const size_t bt0 = (size_t)blockIdx.x * 32;

    for (int idx = tid; idx < D_ * H_; idx += 256) {
        int d = idx >> 6, jj = idx & 63;
        Wp[idx] = make_ulonglong2(
            pack2(Wih0[(jj      ) * D_ + d], Wih0[(jj +  64) * D_ + d]),
            pack2(Wih0[(jj + 128) * D_ + d], Wih0[(jj + 192) * D_ + d]));
    }
    for (int idx = tid; idx < 32 * D_; idx += 256) {
        int r = idx / D_, d = idx - r * D_;
        xd[d * PPX + r] = dup2(x[(bt0 + r) * D_ + d]);
    }
    const ull bif = pack2(bih0[j      ] + bhh0[j      ], bih0[j +  64] + bhh0[j +  64]);
    const ull bgo = pack2(bih0[j + 128] + bhh0[j + 128], bih0[j + 192] + bhh0[j + 192]);
    __syncthreads();

    ull aif[8], ago[8];
    #pragma unroll
    for (int r = 0; r < 8; r++) { aif[r] = bif; ago[r] = bgo; }

    #pragma unroll 6
    for (int d = 0; d < D_; d++) {
        ulonglong2 w = Wp[d * 64 + j];
        const ull* xr = &xd[d * PPX + r0];
        ulonglong2 xA = *(const ulonglong2*)&xr[0];
        ulonglong2 xB = *(const ulonglong2*)&xr[2];
        ulonglong2 xC = *(const ulonglong2*)&xr[4];
        ulonglong2 xD = *(const ulonglong2*)&xr[6];
        fma2(aif[0], w.x, xA.x); fma2(ago[0], w.y, xA.x);
        fma2(aif[1], w.x, xA.y); fma2(ago[1], w.y, xA.y);
        fma2(aif[2], w.x, xB.x); fma2(ago[2], w.y, xB.x);
        fma2(aif[3], w.x, xB.y); fma2(ago[3], w.y, xB.y);
        fma2(aif[4], w.x, xC.x); fma2(ago[4], w.y, xC.x);
        fma2(aif[5], w.x, xC.y); fma2(ago[5], w.y, xC.y);
        fma2(aif[6], w.x, xD.x); fma2(ago[6], w.y, xD.x);
        fma2(aif[7], w.x, xD.y); fma2(ago[7], w.y, xD.y);
    }
    #pragma unroll
    for (int r = 0; r < 8; r++) {
        size_t bt = bt0 + r0 + r;
        size_t b  = bt / T_;
        size_t t  = bt - b * T_;
        g_gx0[(t * B_ + b) * H_ + j] = make_ulonglong2(aif[r], ago[r]);
    }
}

// ============================================================================
// Recurrent kernel: 128 blocks x 16 rows, 128 threads.
// Thread (j = tid&63, rq = tid>>6) owns hidden unit j for rows rq*8..rq*8+7.
// Halves weight-LDS redundancy vs the 256-thread/4-row version.
// ============================================================================
#define HP        20                                     // h pitch in floats
#define HBUF      (64 * HP)                              // floats per buffer
#define SMEM_REC  (3 * 64 * 64 * 16 + 3 * HBUF * 4)      // 196608 + 15360 = 211968 B

__global__ void __launch_bounds__(128, 1)
lstm_rec(const float* __restrict__ Whh0,
         const float* __restrict__ Wih1,
         const float* __restrict__ Whh1,
         const float* __restrict__ bih1,
         const float* __restrict__ bhh1,
         const float* __restrict__ Wfc,
         const float* __restrict__ bfc,
         float* __restrict__ out)
{
    extern __shared__ char sm[];
    ulonglong2* W0p  = (ulonglong2*)sm;          // [k*64 + j], 64KB
    ulonglong2* W1ip = W0p  + 64 * 64;           // 64KB
    ulonglong2* W1hp = W1ip + 64 * 64;           // 64KB
    float*      h0d  = (float*)(W1hp + 64 * 64); // 2 buffers of HBUF
    float*      h1d  = h0d + 2 * HBUF;           // 1 buffer

    const int tid  = threadIdx.x;
    const int j    = tid & 63;
    const int rq   = tid >> 6;                   // 0..1
    const int base = blockIdx.x * 16;
    const int ro   = rq * 8;                     // first of this thread's 8 rows

    for (int idx = tid; idx < 64 * 64; idx += 128) {
        int k = idx >> 6, jj = idx & 63;
        W0p[idx]  = make_ulonglong2(
            pack2(Whh0[(jj      ) * 64 + k], Whh0[(jj +  64) * 64 + k]),
            pack2(Whh0[(jj + 128) * 64 + k], Whh0[(jj + 192) * 64 + k]));
        W1ip[idx] = make_ulonglong2(
            pack2(Wih1[(jj      ) * 64 + k], Wih1[(jj +  64) * 64 + k]),
            pack2(Wih1[(jj + 128) * 64 + k], Wih1[(jj + 192) * 64 + k]));
        W1hp[idx] = make_ulonglong2(
            pack2(Whh1[(jj      ) * 64 + k], Whh1[(jj +  64) * 64 + k]),
            pack2(Whh1[(jj + 128) * 64 + k], Whh1[(jj + 192) * 64 + k]));
    }
    const ull b1if = pack2(bih1[j      ] + bhh1[j      ], bih1[j +  64] + bhh1[j +  64]);
    const ull b1go = pack2(bih1[j + 128] + bhh1[j + 128], bih1[j + 192] + bhh1[j + 192]);
    for (int idx = tid; idx < 3 * HBUF; idx += 128) h0d[idx] = 0.0f;  // h0 bufs + h1
    __syncthreads();

    float c0[8] = {0.f,0.f,0.f,0.f,0.f,0.f,0.f,0.f};
    float c1[8] = {0.f,0.f,0.f,0.f,0.f,0.f,0.f,0.f};

    ulonglong2 gx[8];
    #pragma unroll
    for (int r = 0; r < 8; r++)
        gx[r] = g_gx0[((size_t)base + ro + r) * H_ + j];     // t = 0

    for (int t = 0; t < T_; t++) {
        ulonglong2 gxn[8];
        if (t + 1 < T_) {
            #pragma unroll
            for (int r = 0; r < 8; r++)
                gxn[r] = g_gx0[((size_t)(t + 1) * B_ + base + ro + r) * H_ + j];
        }
        const float* h0r = h0d + (t & 1) * HBUF;         // prev-step h0
        float*       h0w = h0d + ((t & 1) ^ 1) * HBUF;   // this-step h0

        // ---------------- layer 0: gates = gx0 + W_hh0 . h0_prev ----------------
        ull aif[8], ago[8];
        #pragma unroll
        for (int r = 0; r < 8; r++) { aif[r] = gx[r].x; ago[r] = gx[r].y; }

        #pragma unroll 4
        for (int k = 0; k < 64; k++) {
            ulonglong2 w  = W0p[k * 64 + j];                   // lane-contig LDS.128
            float4 hA = *(const float4*)&h0r[k * HP + ro];     // warp-uniform bcast
            float4 hB = *(const float4*)&h0r[k * HP + ro + 4];
            ull d0 = dupf(hA.x), d1 = dupf(hA.y), d2 = dupf(hA.z), d3 = dupf(hA.w);
            ull d4 = dupf(hB.x), d5 = dupf(hB.y), d6 = dupf(hB.z), d7 = dupf(hB.w);
            fma2(aif[0], w.x, d0); fma2(ago[0], w.y, d0);
            fma2(aif[1], w.x, d1); fma2(ago[1], w.y, d1);
            fma2(aif[2], w.x, d2); fma2(ago[2], w.y, d2);
            fma2(aif[3], w.x, d3); fma2(ago[3], w.y, d3);
            fma2(aif[4], w.x, d4); fma2(ago[4], w.y, d4);
            fma2(aif[5], w.x, d5); fma2(ago[5], w.y, d5);
            fma2(aif[6], w.x, d6); fma2(ago[6], w.y, d6);
            fma2(aif[7], w.x, d7); fma2(ago[7], w.y, d7);
        }
        float h0n[8];
        #pragma unroll
        for (int r = 0; r < 8; r++) {
            float i_ = sigf(lo32(aif[r])),  f_ = sigf(hi32(aif[r]));
            float g_ = tanhf_(lo32(ago[r])), o_ = sigf(hi32(ago[r]));
            c0[r]  = f_ * c0[r] + i_ * g_;
            h0n[r] = o_ * tanhf_(c0[r]);
        }
        // write to the OTHER buffer: no read-hazard with in-flight layer-0 reads
        *(float4*)&h0w[j * HP + ro]     = make_float4(h0n[0], h0n[1], h0n[2], h0n[3]);
        *(float4*)&h0w[j * HP + ro + 4] = make_float4(h0n[4], h0n[5], h0n[6], h0n[7]);
        __syncthreads();   // B1: new h0 visible to layer 1

        // -------- layer 1: gates = b1 + W_ih1 . h0_new + W_hh1 . h1_prev --------
        ull bif_[8], bgo_[8];
        #pragma unroll
        for (int r = 0; r < 8; r++) { bif_[r] = b1if; bgo_[r] = b1go; }

        #pragma unroll 2
        for (int k = 0; k < 64; k++) {
            ulonglong2 wi = W1ip[k * 64 + j];
            ulonglong2 wh = W1hp[k * 64 + j];
            float4 eA = *(const float4*)&h0w[k * HP + ro];
            float4 eB = *(const float4*)&h0w[k * HP + ro + 4];
            float4 pA = *(const float4*)&h1d[k * HP + ro];
            float4 pB = *(const float4*)&h1d[k * HP + ro + 4];
            ull e0 = dupf(eA.x), e1 = dupf(eA.y), e2 = dupf(eA.z), e3 = dupf(eA.w);
            ull e4 = dupf(eB.x), e5 = dupf(eB.y), e6 = dupf(eB.z), e7 = dupf(eB.w);
            fma2(bif_[0], wi.x, e0); fma2(bgo_[0], wi.y, e0);
            fma2(bif_[1], wi.x, e1); fma2(bgo_[1], wi.y, e1);
            fma2(bif_[2], wi.x, e2); fma2(bgo_[2], wi.y, e2);
            fma2(bif_[3], wi.x, e3); fma2(bgo_[3], wi.y, e3);
            fma2(bif_[4], wi.x, e4); fma2(bgo_[4], wi.y, e4);
            fma2(bif_[5], wi.x, e5); fma2(bgo_[5], wi.y, e5);
            fma2(bif_[6], wi.x, e6); fma2(bgo_[6], wi.y, e6);
            fma2(bif_[7], wi.x, e7); fma2(bgo_[7], wi.y, e7);
            ull p0 = dupf(pA.x), p1 = dupf(pA.y), p2 = dupf(pA.z), p3 = dupf(pA.w);
            ull p4 = dupf(pB.x), p5 = dupf(pB.y), p6 = dupf(pB.z), p7 = dupf(pB.w);
            fma2(bif_[0], wh.x, p0); fma2(bgo_[0], wh.y, p0);
            fma2(bif_[1], wh.x, p1); fma2(bgo_[1], wh.y, p1);
            fma2(bif_[2], wh.x, p2); fma2(bgo_[2], wh.y, p2);
            fma2(bif_[3], wh.x, p3); fma2(bgo_[3], wh.y, p3);
            fma2(bif_[4], wh.x, p4); fma2(bgo_[4], wh.y, p4);
            fma2(bif_[5], wh.x, p5); fma2(bgo_[5], wh.y, p5);
            fma2(bif_[6], wh.x, p6); fma2(bgo_[6], wh.y, p6);
            fma2(bif_[7], wh.x, p7); fma2(bgo_[7], wh.y, p7);
        }
        float h1n[8];
        #pragma unroll
        for (int r = 0; r < 8; r++) {
            float i_ = sigf(lo32(bif_[r])),  f_ = sigf(hi32(bif_[r]));
            float g_ = tanhf_(lo32(bgo_[r])), o_ = sigf(hi32(bgo_[r]));
            c1[r]  = f_ * c1[r] + i_ * g_;
            h1n[r] = o_ * tanhf_(c1[r]);
        }
        __syncthreads();   // B2: all layer-1 reads of old h1 (and h0w) done
        *(float4*)&h1d[j * HP + ro]     = make_float4(h1n[0], h1n[1], h1n[2], h1n[3]);
        *(float4*)&h1d[j * HP + ro + 4] = make_float4(h1n[4], h1n[5], h1n[6], h1n[7]);
        // h1 writes are made visible to next step's layer 1 by its B1.

        #pragma unroll
        for (int r = 0; r < 8; r++) gx[r] = gxn[r];
    }

    __syncthreads();       // final h1 visible for fc
    // ---------------- fc (64 -> 5) + softmax on final h1 ----------------
    if (tid < 16) {
        const int row = tid;
        const int b   = base + row;
        float lg[5];
        float mx = -1e30f;
        #pragma unroll
        for (int o = 0; o < 5; o++) {
            float s = bfc[o];
            #pragma unroll 8
            for (int k = 0; k < 64; k++)
                s += h1d[k * HP + row] * Wfc[o * 64 + k];
            lg[o] = s;
            mx = fmaxf(mx, s);
        }
        float e[5], den = 0.0f;
        #pragma unroll
        for (int o = 0; o < 5; o++) { e[o] = __expf(lg[o] - mx); den += e[o]; }
        float inv = __fdividef(1.0f, den);
        #pragma unroll
        for (int o = 0; o < 5; o++) out[(size_t)b * 5 + o] = e[o] * inv;
    }
}

// ============================================================================
extern "C" void kernel_launch(void* const* d_in, const int* in_sizes, int n_in,
                              void* d_out, int out_size)
{
    const float* x    = (const float*)d_in[0];
    const float* Wih0 = (const float*)d_in[1];
    const float* Whh0 = (const float*)d_in[2];
    const float* bih0 = (const float*)d_in[3];
    const float* bhh0 = (const float*)d_in[4];
    const float* Wih1 = (const float*)d_in[5];
    const float* Whh1 = (const float*)d_in[6];
    const float* bih1 = (const float*)d_in[7];
    const float* bhh1 = (const float*)d_in[8];
    const float* Wfc  = (const float*)d_in[9];
    const float* bfc  = (const float*)d_in[10];
    float* out = (float*)d_out;

    cudaFuncSetAttribute(gx0_prepass, cudaFuncAttributeMaxDynamicSharedMemorySize, PP_SMEM);
    cudaFuncSetAttribute(lstm_rec,    cudaFuncAttributeMaxDynamicSharedMemorySize, SMEM_REC);

    gx0_prepass<<<(B_ * T_) / 32, 256, PP_SMEM>>>(x, Wih0, bih0, bhh0);
    lstm_rec<<<B_ / 16, 128, SMEM_REC>>>(Whh0, Wih1, Whh1, bih1, bhh1, Wfc, bfc, out);
}

// round 9
// speedup vs baseline: 1.3890x; 1.3890x over previous
#include <cuda_runtime.h>
#include <cstdint>
#include <cstddef>

#define B_  2048
#define T_  256
#define D_  42
#define H_  64

typedef unsigned long long ull;

// 512MB scratch: gate-packed layer-0 preactivations, {(i,f),(g,o)} per (t,b,j)
__device__ ulonglong2 g_gx0[(size_t)B_ * T_ * H_];

// ---------------------------------------------------------------- helpers ---
__device__ __forceinline__ void fma2(ull& d, ull a, ull b) {
    // packed fp32x2 FMA: d = a*b + d  (two IEEE fp32 MACs per instruction)
    asm("fma.rn.f32x2 %0, %1, %2, %0;" : "+l"(d) : "l"(a), "l"(b));
}
__device__ __forceinline__ ull dupf(float v) {
    unsigned r = __float_as_uint(v);
    ull d; asm("mov.b64 %0, {%1, %1};" : "=l"(d) : "r"(r));
    return d;
}
__device__ __forceinline__ ull dup2(float v) {
    ull u = (ull)__float_as_uint(v); return u | (u << 32);
}
__device__ __forceinline__ ull pack2(float lo, float hi) {
    return (ull)__float_as_uint(lo) | ((ull)__float_as_uint(hi) << 32);
}
__device__ __forceinline__ float lo32(ull u) { return __uint_as_float((unsigned)u); }
__device__ __forceinline__ float hi32(ull u) { return __uint_as_float((unsigned)(u >> 32)); }
__device__ __forceinline__ ull shfl16(ull v) {
    return (ull)__shfl_xor_sync(0xffffffffu, (long long)v, 16);
}
__device__ __forceinline__ float sigf(float x)   { return __fdividef(1.0f, 1.0f + __expf(-x)); }
__device__ __forceinline__ float tanhf_(float x) { float e = __expf(2.0f * x); return 1.0f - __fdividef(2.0f, e + 1.0f); }

// ============================================================================
// Prepass: gx0[t][b][j] = x[b,t,:] . W_ih0^T + b_ih0 + b_hh0   (gate-packed)
// 32 (b,t) rows per block; thread (j = tid&63, slot = tid>>6) does 8 rows.
// ============================================================================
#define PPX      34                             // x-dup pitch in ulls (even)
#define PP_SMEM  (D_ * H_ * 16 + D_ * PPX * 8)  // 43008 + 11424 = 54432 B

__global__ void __launch_bounds__(256, 2)
gx0_prepass(const float* __restrict__ x,
            const float* __restrict__ Wih0,
            const float* __restrict__ bih0,
            const float* __restrict__ bhh0)
{
    extern __shared__ char sm[];
    ulonglong2* Wp = (ulonglong2*)sm;            // [d*64 + j] {(i,f),(g,o)}
    ull*        xd = (ull*)(sm + D_ * H_ * 16);  // [d*PPX + row] duplicated x

    const int tid  = threadIdx.x;
    const int j    = tid & 63;
    const int slot = tid >> 6;                   // 0..3
    const int r0   = slot * 8;                   // first of this thread's 8 rows
    const size_t bt0 = (size_t)blockIdx.x * 32;

    for (int idx = tid; idx < D_ * H_; idx += 256) {
        int d = idx >> 6, jj = idx & 63;
        Wp[idx] = make_ulonglong2(
            pack2(Wih0[(jj      ) * D_ + d], Wih0[(jj +  64) * D_ + d]),
            pack2(Wih0[(jj + 128) * D_ + d], Wih0[(jj + 192) * D_ + d]));
    }
    for (int idx = tid; idx < 32 * D_; idx += 256) {
        int r = idx / D_, d = idx - r * D_;
        xd[d * PPX + r] = dup2(x[(bt0 + r) * D_ + d]);
    }
    const ull bif = pack2(bih0[j      ] + bhh0[j      ], bih0[j +  64] + bhh0[j +  64]);
    const ull bgo = pack2(bih0[j + 128] + bhh0[j + 128], bih0[j + 192] + bhh0[j + 192]);
    __syncthreads();

    ull aif[8], ago[8];
    #pragma unroll
    for (int r = 0; r < 8; r++) { aif[r] = bif; ago[r] = bgo; }

    #pragma unroll 6
    for (int d = 0; d < D_; d++) {
        ulonglong2 w = Wp[d * 64 + j];
        const ull* xr = &xd[d * PPX + r0];
        ulonglong2 xA = *(const ulonglong2*)&xr[0];
        ulonglong2 xB = *(const ulonglong2*)&xr[2];
        ulonglong2 xC = *(const ulonglong2*)&xr[4];
        ulonglong2 xD = *(const ulonglong2*)&xr[6];
        fma2(aif[0], w.x, xA.x); fma2(ago[0], w.y, xA.x);
        fma2(aif[1], w.x, xA.y); fma2(ago[1], w.y, xA.y);
        fma2(aif[2], w.x, xB.x); fma2(ago[2], w.y, xB.x);
        fma2(aif[3], w.x, xB.y); fma2(ago[3], w.y, xB.y);
        fma2(aif[4], w.x, xC.x); fma2(ago[4], w.y, xC.x);
        fma2(aif[5], w.x, xC.y); fma2(ago[5], w.y, xC.y);
        fma2(aif[6], w.x, xD.x); fma2(ago[6], w.y, xD.x);
        fma2(aif[7], w.x, xD.y); fma2(ago[7], w.y, xD.y);
    }
    #pragma unroll
    for (int r = 0; r < 8; r++) {
        size_t bt = bt0 + r0 + r;
        size_t b  = bt / T_;
        size_t t  = bt - b * T_;
        g_gx0[(t * B_ + b) * H_ + j] = make_ulonglong2(aif[r], ago[r]);
    }
}

// ============================================================================
// Recurrent kernel: 128 blocks x 16 rows, 256 threads (8 warps, 2/SMSP).
// Thread: lane = jlo + 16*gp  (gp: 0 = gates (i,f), 1 = gates (g,o))
//         warp w: jhi = w&3 (j = jhi*16+jlo), rq = w>>2 (8 rows each).
// Each thread computes its 2 gates for 8 rows (row-pair f32x2 accumulators),
// then exchanges with partner lane^16 to assemble full gates for 4 rows.
// Weight LDS per k = one LDS.64/lane (warp covers contiguous 256B = 2 wf).
// ============================================================================
#define HP        20                                     // h pitch in floats
#define HBUF      (64 * HP)                              // floats per buffer
#define SMEM_REC  (3 * 64 * 64 * 16 + 3 * HBUF * 4)      // 196608 + 15360 = 211968 B

__global__ void __launch_bounds__(256, 1)
lstm_rec(const float* __restrict__ Whh0,
         const float* __restrict__ Wih1,
         const float* __restrict__ Whh1,
         const float* __restrict__ bih1,
         const float* __restrict__ bhh1,
         const float* __restrict__ Wfc,
         const float* __restrict__ bfc,
         float* __restrict__ out)
{
    extern __shared__ char sm[];
    ulonglong2* W0p  = (ulonglong2*)sm;          // [k*64 + j], 64KB
    ulonglong2* W1ip = W0p  + 64 * 64;           // 64KB
    ulonglong2* W1hp = W1ip + 64 * 64;           // 64KB
    float*      h0d  = (float*)(W1hp + 64 * 64); // 2 buffers of HBUF
    float*      h1d  = h0d + 2 * HBUF;           // 1 buffer
    const ull*  W0u  = (const ull*)W0p;
    const ull*  W1iu = (const ull*)W1ip;
    const ull*  W1hu = (const ull*)W1hp;

    const int tid  = threadIdx.x;
    const int lane = tid & 31;
    const int wrp  = tid >> 5;                   // 0..7
    const int jlo  = lane & 15;
    const int gp   = lane >> 4;                  // 0: (i,f), 1: (g,o)
    const int jhi  = wrp & 3;
    const int rq   = wrp >> 2;                   // 0..1
    const int j    = jhi * 16 + jlo;
    const int base = blockIdx.x * 16;
    const int ro   = rq * 8;                     // warp-group's 8 rows
    const int rown = ro + gp * 4;                // this thread's 4 owned rows

    // Gate-pack weights (same layout as before: ulonglong2 {(i,f),(g,o)})
    for (int idx = tid; idx < 64 * 64; idx += 256) {
        int k = idx >> 6, jj = idx & 63;
        W0p[idx]  = make_ulonglong2(
            pack2(Whh0[(jj      ) * 64 + k], Whh0[(jj +  64) * 64 + k]),
            pack2(Whh0[(jj + 128) * 64 + k], Whh0[(jj + 192) * 64 + k]));
        W1ip[idx] = make_ulonglong2(
            pack2(Wih1[(jj      ) * 64 + k], Wih1[(jj +  64) * 64 + k]),
            pack2(Wih1[(jj + 128) * 64 + k], Wih1[(jj + 192) * 64 + k]));
        W1hp[idx] = make_ulonglong2(
            pack2(Whh1[(jj      ) * 64 + k], Whh1[(jj +  64) * 64 + k]),
            pack2(Whh1[(jj + 128) * 64 + k], Whh1[(jj + 192) * 64 + k]));
    }
    // layer-1 biases for this thread's two gates (gA = 2*gp, gB = 2*gp+1)
    const int gA = 2 * gp, gB = 2 * gp + 1;
    const ull b1A = dup2(bih1[gA * 64 + j] + bhh1[gA * 64 + j]);
    const ull b1B = dup2(bih1[gB * 64 + j] + bhh1[gB * 64 + j]);
    for (int idx = tid; idx < 3 * HBUF; idx += 256) h0d[idx] = 0.0f;  // h0 bufs + h1
    __syncthreads();

    float c0[4] = {0.f, 0.f, 0.f, 0.f};      // cell state for the 4 owned rows
    float c1[4] = {0.f, 0.f, 0.f, 0.f};

    // gx0 loads: this thread's gate-half only (LDG.64) for its warp-group's 8 rows
    const ull* gxg = (const ull*)g_gx0;
    ull lg[8];
    #pragma unroll
    for (int r = 0; r < 8; r++)
        lg[r] = gxg[(((size_t)base + ro + r) * H_ + j) * 2 + gp];     // t = 0

    for (int t = 0; t < T_; t++) {
        ull lgn[8];
        if (t + 1 < T_) {
            #pragma unroll
            for (int r = 0; r < 8; r++)
                lgn[r] = gxg[(((size_t)(t + 1) * B_ + base + ro + r) * H_ + j) * 2 + gp];
        }
        const float* h0r = h0d + (t & 1) * HBUF;         // prev-step h0
        float*       h0w = h0d + ((t & 1) ^ 1) * HBUF;   // this-step h0

        // ---------------- layer 0: acc = gx0 + W_hh0 . h0_prev ----------------
        // row-pair accumulators: accA/accB[rp] = gate A/B for rows (2rp, 2rp+1)
        ull accA[4], accB[4];
        #pragma unroll
        for (int p = 0; p < 4; p++) {
            accA[p] = pack2(lo32(lg[2*p]), lo32(lg[2*p + 1]));
            accB[p] = pack2(hi32(lg[2*p]), hi32(lg[2*p + 1]));
        }
        #pragma unroll 4
        for (int k = 0; k < 64; k++) {
            ull w0 = W0u[(k * 64 + j) * 2 + gp];               // 2wf/warp
            ulonglong2 hA = *(const ulonglong2*)&h0r[k * HP + ro];      // bcast
            ulonglong2 hB = *(const ulonglong2*)&h0r[k * HP + ro + 4];  // bcast
            ull wA = dupf(lo32(w0)), wB = dupf(hi32(w0));
            fma2(accA[0], wA, hA.x); fma2(accB[0], wB, hA.x);
            fma2(accA[1], wA, hA.y); fma2(accB[1], wB, hA.y);
            fma2(accA[2], wA, hB.x); fma2(accB[2], wB, hB.x);
            fma2(accA[3], wA, hB.y); fma2(accB[3], wB, hB.y);
        }
        // exchange: gp0 keeps rp0,1 (rows ro..ro+3), gp1 keeps rp2,3
        {
            ull rA0 = shfl16(gp ? accA[0] : accA[2]);
            ull rA1 = shfl16(gp ? accA[1] : accA[3]);
            ull rB0 = shfl16(gp ? accB[0] : accB[2]);
            ull rB1 = shfl16(gp ? accB[1] : accB[3]);
            ull I[2], F[2], G[2], O[2];
            I[0] = gp ? rA0 : accA[0];  I[1] = gp ? rA1 : accA[1];
            F[0] = gp ? rB0 : accB[0];  F[1] = gp ? rB1 : accB[1];
            G[0] = gp ? accA[2] : rA0;  G[1] = gp ? accA[3] : rA1;
            O[0] = gp ? accB[2] : rB0;  O[1] = gp ? accB[3] : rB1;
            float h0n[4];
            #pragma unroll
            for (int p = 0; p < 2; p++) {
                float i0 = sigf(lo32(I[p])),   i1 = sigf(hi32(I[p]));
                float f0 = sigf(lo32(F[p])),   f1 = sigf(hi32(F[p]));
                float g0 = tanhf_(lo32(G[p])), g1 = tanhf_(hi32(G[p]));
                float o0 = sigf(lo32(O[p])),   o1 = sigf(hi32(O[p]));
                c0[2*p]   = f0 * c0[2*p]   + i0 * g0;  h0n[2*p]   = o0 * tanhf_(c0[2*p]);
                c0[2*p+1] = f1 * c0[2*p+1] + i1 * g1;  h0n[2*p+1] = o1 * tanhf_(c0[2*p+1]);
            }
            *(float4*)&h0w[j * HP + rown] = make_float4(h0n[0], h0n[1], h0n[2], h0n[3]);
        }
        __syncthreads();   // B1: new h0 visible to layer 1 (and prev h1 writes)

        // -------- layer 1: acc = b1 + W_ih1 . h0_new + W_hh1 . h1_prev --------
        ull dA[4], dB[4];
        #pragma unroll
        for (int p = 0; p < 4; p++) { dA[p] = b1A; dB[p] = b1B; }

        #pragma unroll 4
        for (int k = 0; k < 64; k++) {
            ull wi = W1iu[(k * 64 + j) * 2 + gp];
            ull wh = W1hu[(k * 64 + j) * 2 + gp];
            ulonglong2 eA = *(const ulonglong2*)&h0w[k * HP + ro];
            ulonglong2 eB = *(const ulonglong2*)&h0w[k * HP + ro + 4];
            ulonglong2 pA = *(const ulonglong2*)&h1d[k * HP + ro];
            ulonglong2 pB = *(const ulonglong2*)&h1d[k * HP + ro + 4];
            ull wiA = dupf(lo32(wi)), wiB = dupf(hi32(wi));
            ull whA = dupf(lo32(wh)), whB = dupf(hi32(wh));
            fma2(dA[0], wiA, eA.x); fma2(dB[0], wiB, eA.x);
            fma2(dA[1], wiA, eA.y); fma2(dB[1], wiB, eA.y);
            fma2(dA[2], wiA, eB.x); fma2(dB[2], wiB, eB.x);
            fma2(dA[3], wiA, eB.y); fma2(dB[3], wiB, eB.y);
            fma2(dA[0], whA, pA.x); fma2(dB[0], whB, pA.x);
            fma2(dA[1], whA, pA.y); fma2(dB[1], whB, pA.y);
            fma2(dA[2], whA, pB.x); fma2(dB[2], whB, pB.x);
            fma2(dA[3], whA, pB.y); fma2(dB[3], whB, pB.y);
        }
        float h1n[4];
        {
            ull rA0 = shfl16(gp ? dA[0] : dA[2]);
            ull rA1 = shfl16(gp ? dA[1] : dA[3]);
            ull rB0 = shfl16(gp ? dB[0] : dB[2]);
            ull rB1 = shfl16(gp ? dB[1] : dB[3]);
            ull I[2], F[2], G[2], O[2];
            I[0] = gp ? rA0 : dA[0];  I[1] = gp ? rA1 : dA[1];
            F[0] = gp ? rB0 : dB[0];  F[1] = gp ? rB1 : dB[1];
            G[0] = gp ? dA[2] : rA0;  G[1] = gp ? dA[3] : rA1;
            O[0] = gp ? dB[2] : rB0;  O[1] = gp ? dB[3] : rB1;
            #pragma unroll
            for (int p = 0; p < 2; p++) {
                float i0 = sigf(lo32(I[p])),   i1 = sigf(hi32(I[p]));
                float f0 = sigf(lo32(F[p])),   f1 = sigf(hi32(F[p]));
                float g0 = tanhf_(lo32(G[p])), g1 = tanhf_(hi32(G[p]));
                float o0 = sigf(lo32(O[p])),   o1 = sigf(hi32(O[p]));
                c1[2*p]   = f0 * c1[2*p]   + i0 * g0;  h1n[2*p]   = o0 * tanhf_(c1[2*p]);
                c1[2*p+1] = f1 * c1[2*p+1] + i1 * g1;  h1n[2*p+1] = o1 * tanhf_(c1[2*p+1]);
            }
        }
        __syncthreads();   // B2: all layer-1 reads of old h1 (and h0w) done
        *(float4*)&h1d[j * HP + rown] = make_float4(h1n[0], h1n[1], h1n[2], h1n[3]);
        // h1 writes are made visible to next step's layer 1 by its B1.

        #pragma unroll
        for (int r = 0; r < 8; r++) lg[r] = lgn[r];
    }

    __syncthreads();       // final h1 visible for fc
    // ---------------- fc (64 -> 5) + softmax on final h1 ----------------
    if (tid < 16) {
        const int row = tid;
        const int b   = base + row;
        float lgt[5];
        float mx = -1e30f;
        #pragma unroll
        for (int o = 0; o < 5; o++) {
            float s = bfc[o];
            #pragma unroll 8
            for (int k = 0; k < 64; k++)
                s += h1d[k * HP + row] * Wfc[o * 64 + k];
            lgt[o] = s;
            mx = fmaxf(mx, s);
        }
        float e[5], den = 0.0f;
        #pragma unroll
        for (int o = 0; o < 5; o++) { e[o] = __expf(lgt[o] - mx); den += e[o]; }
        float inv = __fdividef(1.0f, den);
        #pragma unroll
        for (int o = 0; o < 5; o++) out[(size_t)b * 5 + o] = e[o] * inv;
    }
}

// ============================================================================
extern "C" void kernel_launch(void* const* d_in, const int* in_sizes, int n_in,
                              void* d_out, int out_size)
{
    const float* x    = (const float*)d_in[0];
    const float* Wih0 = (const float*)d_in[1];
    const float* Whh0 = (const float*)d_in[2];
    const float* bih0 = (const float*)d_in[3];
    const float* bhh0 = (const float*)d_in[4];
    const float* Wih1 = (const float*)d_in[5];
    const float* Whh1 = (const float*)d_in[6];
    const float* bih1 = (const float*)d_in[7];
    const float* bhh1 = (const float*)d_in[8];
    const float* Wfc  = (const float*)d_in[9];
    const float* bfc  = (const float*)d_in[10];
    float* out = (float*)d_out;

    cudaFuncSetAttribute(gx0_prepass, cudaFuncAttributeMaxDynamicSharedMemorySize, PP_SMEM);
    cudaFuncSetAttribute(lstm_rec,    cudaFuncAttributeMaxDynamicSharedMemorySize, SMEM_REC);

    gx0_prepass<<<(B_ * T_) / 32, 256, PP_SMEM>>>(x, Wih0, bih0, bhh0);
    lstm_rec<<<B_ / 16, 256, SMEM_REC>>>(Whh0, Wih1, Whh1, bih1, bhh1, Wfc, bfc, out);
}

// round 10
// speedup vs baseline: 1.7579x; 1.2656x over previous
#include <cuda_runtime.h>
#include <cstdint>
#include <cstddef>

#define B_  2048
#define T_  256
#define D_  42
#define H_  64

typedef unsigned long long ull;

// 512MB scratch: gate-packed layer-0 preactivations, {(i,f),(g,o)} per (t,b,j)
__device__ ulonglong2 g_gx0[(size_t)B_ * T_ * H_];

// ---------------------------------------------------------------- helpers ---
__device__ __forceinline__ void fma2(ull& d, ull a, ull b) {
    asm("fma.rn.f32x2 %0, %1, %2, %0;" : "+l"(d) : "l"(a), "l"(b));
}
__device__ __forceinline__ void add2(ull& d, ull a) {
    asm("add.rn.f32x2 %0, %0, %1;" : "+l"(d) : "l"(a));
}
__device__ __forceinline__ ull dupf(float v) {
    unsigned r = __float_as_uint(v);
    ull d; asm("mov.b64 %0, {%1, %1};" : "=l"(d) : "r"(r));
    return d;
}
__device__ __forceinline__ ull dup2(float v) {
    ull u = (ull)__float_as_uint(v); return u | (u << 32);
}
__device__ __forceinline__ ull pack2(float lo, float hi) {
    return (ull)__float_as_uint(lo) | ((ull)__float_as_uint(hi) << 32);
}
__device__ __forceinline__ float lo32(ull u) { return __uint_as_float((unsigned)u); }
__device__ __forceinline__ float hi32(ull u) { return __uint_as_float((unsigned)(u >> 32)); }
__device__ __forceinline__ float sigf(float x)   { return __fdividef(1.0f, 1.0f + __expf(-x)); }
__device__ __forceinline__ float tanhf_(float x) { float e = __expf(2.0f * x); return 1.0f - __fdividef(2.0f, e + 1.0f); }

// ============================================================================
// Prepass: gx0[t][b][j] = x[b,t,:] . W_ih0^T + b_ih0 + b_hh0   (gate-packed)
// ============================================================================
#define PPX      34
#define PP_SMEM  (D_ * H_ * 16 + D_ * PPX * 8)  // 54432 B

__global__ void __launch_bounds__(256, 2)
gx0_prepass(const float* __restrict__ x,
            const float* __restrict__ Wih0,
            const float* __restrict__ bih0,
            const float* __restrict__ bhh0)
{
    extern __shared__ char sm[];
    ulonglong2* Wp = (ulonglong2*)sm;            // [d*64 + j] {(i,f),(g,o)}
    ull*        xd = (ull*)(sm + D_ * H_ * 16);  // [d*PPX + row] duplicated x

    const int tid  = threadIdx.x;
    const int j    = tid & 63;
    const int slot = tid >> 6;
    const int r0   = slot * 8;
    const size_t bt0 = (size_t)blockIdx.x * 32;

    for (int idx = tid; idx < D_ * H_; idx += 256) {
        int d = idx >> 6, jj = idx & 63;
        Wp[idx] = make_ulonglong2(
            pack2(Wih0[(jj      ) * D_ + d], Wih0[(jj +  64) * D_ + d]),
            pack2(Wih0[(jj + 128) * D_ + d], Wih0[(jj + 192) * D_ + d]));
    }
    for (int idx = tid; idx < 32 * D_; idx += 256) {
        int r = idx / D_, d = idx - r * D_;
        xd[d * PPX + r] = dup2(x[(bt0 + r) * D_ + d]);
    }
    const ull bif = pack2(bih0[j      ] + bhh0[j      ], bih0[j +  64] + bhh0[j +  64]);
    const ull bgo = pack2(bih0[j + 128] + bhh0[j + 128], bih0[j + 192] + bhh0[j + 192]);
    __syncthreads();

    ull aif[8], ago[8];
    #pragma unroll
    for (int r = 0; r < 8; r++) { aif[r] = bif; ago[r] = bgo; }

    #pragma unroll 6
    for (int d = 0; d < D_; d++) {
        ulonglong2 w = Wp[d * 64 + j];
        const ull* xr = &xd[d * PPX + r0];
        ulonglong2 xA = *(const ulonglong2*)&xr[0];
        ulonglong2 xB = *(const ulonglong2*)&xr[2];
        ulonglong2 xC = *(const ulonglong2*)&xr[4];
        ulonglong2 xD = *(const ulonglong2*)&xr[6];
        fma2(aif[0], w.x, xA.x); fma2(ago[0], w.y, xA.x);
        fma2(aif[1], w.x, xA.y); fma2(ago[1], w.y, xA.y);
        fma2(aif[2], w.x, xB.x); fma2(ago[2], w.y, xB.x);
        fma2(aif[3], w.x, xB.y); fma2(ago[3], w.y, xB.y);
        fma2(aif[4], w.x, xC.x); fma2(ago[4], w.y, xC.x);
        fma2(aif[5], w.x, xC.y); fma2(ago[5], w.y, xC.y);
        fma2(aif[6], w.x, xD.x); fma2(ago[6], w.y, xD.x);
        fma2(aif[7], w.x, xD.y); fma2(ago[7], w.y, xD.y);
    }
    #pragma unroll
    for (int r = 0; r < 8; r++) {
        size_t bt = bt0 + r0 + r;
        size_t b  = bt / T_;
        size_t t  = bt - b * T_;
        g_gx0[(t * B_ + b) * H_ + j] = make_ulonglong2(aif[r], ago[r]);
    }
}

// ============================================================================
// Recurrent kernel: 128 blocks x 16 rows, 256 threads (8 warps).
// Warp bits: jhi = w&1 (j = jhi*32 + lane), rq = (w>>1)&1 (8 rows),
//            kh = w>>2 (k-half: 32 k). Each SMSP hosts one kh0 + one kh1 warp.
// kh-partials merged via smem scratch; kh0 warps do cell updates + h writes.
// Load shapes identical to the proven R7 kernel (LDS.128 weights, float4
// h broadcasts, gate-packed FFMA2 with register h-dups).
// ============================================================================
#define HP        20                                     // h pitch in floats
#define HBUF      (64 * HP)                              // 1280 floats / buffer
#define SCR_OFF   (3 * 64 * 64 * 16 + 3 * HBUF * 4)      // 211968
#define SMEM_REC  (SCR_OFF + 16 * 128 * 8)               // + 16384 = 228352 B

__global__ void __launch_bounds__(256, 1)
lstm_rec(const float* __restrict__ Whh0,
         const float* __restrict__ Wih1,
         const float* __restrict__ Whh1,
         const float* __restrict__ bih1,
         const float* __restrict__ bhh1,
         const float* __restrict__ Wfc,
         const float* __restrict__ bfc,
         float* __restrict__ out)
{
    extern __shared__ char sm[];
    ulonglong2* W0p  = (ulonglong2*)sm;          // [k*64 + j], 64KB
    ulonglong2* W1ip = W0p  + 64 * 64;           // 64KB
    ulonglong2* W1hp = W1ip + 64 * 64;           // 64KB
    float*      h0d  = (float*)(W1hp + 64 * 64); // 2 buffers of HBUF
    float*      h1d  = h0d + 2 * HBUF;           // 1 buffer
    ull*        scr  = (ull*)(sm + SCR_OFF);     // [16][128] partials

    const int tid  = threadIdx.x;
    const int lane = tid & 31;
    const int wrp  = tid >> 5;                   // 0..7
    const int jhi  = wrp & 1;
    const int rq   = (wrp >> 1) & 1;             // 0..1 (8 rows each)
    const int kh   = wrp >> 2;                   // 0..1 (32 k each)
    const int j    = jhi * 32 + lane;
    const int base = blockIdx.x * 16;
    const int ro   = rq * 8;
    const int kb   = kh * 32;                    // k-range start

    for (int idx = tid; idx < 64 * 64; idx += 256) {
        int k = idx >> 6, jj = idx & 63;
        W0p[idx]  = make_ulonglong2(
            pack2(Whh0[(jj      ) * 64 + k], Whh0[(jj +  64) * 64 + k]),
            pack2(Whh0[(jj + 128) * 64 + k], Whh0[(jj + 192) * 64 + k]));
        W1ip[idx] = make_ulonglong2(
            pack2(Wih1[(jj      ) * 64 + k], Wih1[(jj +  64) * 64 + k]),
            pack2(Wih1[(jj + 128) * 64 + k], Wih1[(jj + 192) * 64 + k]));
        W1hp[idx] = make_ulonglong2(
            pack2(Whh1[(jj      ) * 64 + k], Whh1[(jj +  64) * 64 + k]),
            pack2(Whh1[(jj + 128) * 64 + k], Whh1[(jj + 192) * 64 + k]));
    }
    const ull b1if = pack2(bih1[j      ] + bhh1[j      ], bih1[j +  64] + bhh1[j +  64]);
    const ull b1go = pack2(bih1[j + 128] + bhh1[j + 128], bih1[j + 192] + bhh1[j + 192]);
    for (int idx = tid; idx < 3 * HBUF; idx += 256) h0d[idx] = 0.0f;
    __syncthreads();

    float c0[8] = {0.f,0.f,0.f,0.f,0.f,0.f,0.f,0.f};
    float c1[8] = {0.f,0.f,0.f,0.f,0.f,0.f,0.f,0.f};

    // gx prefetch: kh0 threads only (they own the accumulator init)
    ulonglong2 gx[8];
    if (kh == 0) {
        #pragma unroll
        for (int r = 0; r < 8; r++)
            gx[r] = g_gx0[((size_t)base + ro + r) * H_ + j];     // t = 0
    }

    for (int t = 0; t < T_; t++) {
        ulonglong2 gxn[8];
        if (kh == 0 && t + 1 < T_) {
            #pragma unroll
            for (int r = 0; r < 8; r++)
                gxn[r] = g_gx0[((size_t)(t + 1) * B_ + base + ro + r) * H_ + j];
        }
        const float* h0r = h0d + (t & 1) * HBUF;         // prev-step h0
        float*       h0w = h0d + ((t & 1) ^ 1) * HBUF;   // this-step h0

        // ---------------- layer 0: partial = [gx0] + W_hh0[kh] . h0_prev ------
        ull aif[8], ago[8];
        if (kh == 0) {
            #pragma unroll
            for (int r = 0; r < 8; r++) { aif[r] = gx[r].x; ago[r] = gx[r].y; }
        } else {
            #pragma unroll
            for (int r = 0; r < 8; r++) { aif[r] = 0ull; ago[r] = 0ull; }
        }
        #pragma unroll 4
        for (int i = 0; i < 32; i++) {
            int k = kb + i;
            ulonglong2 w  = W0p[k * 64 + j];                   // lane-contig LDS.128
            float4 hA = *(const float4*)&h0r[k * HP + ro];     // warp-uniform bcast
            float4 hB = *(const float4*)&h0r[k * HP + ro + 4];
            ull d0 = dupf(hA.x), d1 = dupf(hA.y), d2 = dupf(hA.z), d3 = dupf(hA.w);
            ull d4 = dupf(hB.x), d5 = dupf(hB.y), d6 = dupf(hB.z), d7 = dupf(hB.w);
            fma2(aif[0], w.x, d0); fma2(ago[0], w.y, d0);
            fma2(aif[1], w.x, d1); fma2(ago[1], w.y, d1);
            fma2(aif[2], w.x, d2); fma2(ago[2], w.y, d2);
            fma2(aif[3], w.x, d3); fma2(ago[3], w.y, d3);
            fma2(aif[4], w.x, d4); fma2(ago[4], w.y, d4);
            fma2(aif[5], w.x, d5); fma2(ago[5], w.y, d5);
            fma2(aif[6], w.x, d6); fma2(ago[6], w.y, d6);
            fma2(aif[7], w.x, d7); fma2(ago[7], w.y, d7);
        }
        if (kh == 1) {                                    // publish partials
            int tl = tid & 127;
            #pragma unroll
            for (int m = 0; m < 8; m++) {
                scr[m * 128 + tl]       = aif[m];
                scr[(m + 8) * 128 + tl] = ago[m];
            }
        }
        __syncthreads();   // BAR1: partials visible; all h0r reads done
        if (kh == 0) {
            #pragma unroll
            for (int m = 0; m < 8; m++) {
                add2(aif[m], scr[m * 128 + tid]);
                add2(ago[m], scr[(m + 8) * 128 + tid]);
            }
            float h0n[8];
            #pragma unroll
            for (int r = 0; r < 8; r++) {
                float i_ = sigf(lo32(aif[r])),  f_ = sigf(hi32(aif[r]));
                float g_ = tanhf_(lo32(ago[r])), o_ = sigf(hi32(ago[r]));
                c0[r]  = f_ * c0[r] + i_ * g_;
                h0n[r] = o_ * tanhf_(c0[r]);
            }
            *(float4*)&h0w[j * HP + ro]     = make_float4(h0n[0], h0n[1], h0n[2], h0n[3]);
            *(float4*)&h0w[j * HP + ro + 4] = make_float4(h0n[4], h0n[5], h0n[6], h0n[7]);
        }
        __syncthreads();   // BAR2: new h0 visible; scratch free for reuse

        // -------- layer 1: partial = [b1] + W_ih1[kh].h0_new + W_hh1[kh].h1 ---
        ull bif_[8], bgo_[8];
        if (kh == 0) {
            #pragma unroll
            for (int r = 0; r < 8; r++) { bif_[r] = b1if; bgo_[r] = b1go; }
        } else {
            #pragma unroll
            for (int r = 0; r < 8; r++) { bif_[r] = 0ull; bgo_[r] = 0ull; }
        }
        #pragma unroll 2
        for (int i = 0; i < 32; i++) {
            int k = kb + i;
            ulonglong2 wi = W1ip[k * 64 + j];
            ulonglong2 wh = W1hp[k * 64 + j];
            float4 eA = *(const float4*)&h0w[k * HP + ro];
            float4 eB = *(const float4*)&h0w[k * HP + ro + 4];
            float4 pA = *(const float4*)&h1d[k * HP + ro];
            float4 pB = *(const float4*)&h1d[k * HP + ro + 4];
            ull e0 = dupf(eA.x), e1 = dupf(eA.y), e2 = dupf(eA.z), e3 = dupf(eA.w);
            ull e4 = dupf(eB.x), e5 = dupf(eB.y), e6 = dupf(eB.z), e7 = dupf(eB.w);
            fma2(bif_[0], wi.x, e0); fma2(bgo_[0], wi.y, e0);
            fma2(bif_[1], wi.x, e1); fma2(bgo_[1], wi.y, e1);
            fma2(bif_[2], wi.x, e2); fma2(bgo_[2], wi.y, e2);
            fma2(bif_[3], wi.x, e3); fma2(bgo_[3], wi.y, e3);
            fma2(bif_[4], wi.x, e4); fma2(bgo_[4], wi.y, e4);
            fma2(bif_[5], wi.x, e5); fma2(bgo_[5], wi.y, e5);
            fma2(bif_[6], wi.x, e6); fma2(bgo_[6], wi.y, e6);
            fma2(bif_[7], wi.x, e7); fma2(bgo_[7], wi.y, e7);
            ull p0 = dupf(pA.x), p1 = dupf(pA.y), p2 = dupf(pA.z), p3 = dupf(pA.w);
            ull p4 = dupf(pB.x), p5 = dupf(pB.y), p6 = dupf(pB.z), p7 = dupf(pB.w);
            fma2(bif_[0], wh.x, p0); fma2(bgo_[0], wh.y, p0);
            fma2(bif_[1], wh.x, p1); fma2(bgo_[1], wh.y, p1);
            fma2(bif_[2], wh.x, p2); fma2(bgo_[2], wh.y, p2);
            fma2(bif_[3], wh.x, p3); fma2(bgo_[3], wh.y, p3);
            fma2(bif_[4], wh.x, p4); fma2(bgo_[4], wh.y, p4);
            fma2(bif_[5], wh.x, p5); fma2(bgo_[5], wh.y, p5);
            fma2(bif_[6], wh.x, p6); fma2(bgo_[6], wh.y, p6);
            fma2(bif_[7], wh.x, p7); fma2(bgo_[7], wh.y, p7);
        }
        if (kh == 1) {
            int tl = tid & 127;
            #pragma unroll
            for (int m = 0; m < 8; m++) {
                scr[m * 128 + tl]       = bif_[m];
                scr[(m + 8) * 128 + tl] = bgo_[m];
            }
        }
        __syncthreads();   // BAR3: partials visible; all h1/h0w reads done
        if (kh == 0) {
            #pragma unroll
            for (int m = 0; m < 8; m++) {
                add2(bif_[m], scr[m * 128 + tid]);
                add2(bgo_[m], scr[(m + 8) * 128 + tid]);
            }
            float h1n[8];
            #pragma unroll
            for (int r = 0; r < 8; r++) {
                float i_ = sigf(lo32(bif_[r])),  f_ = sigf(hi32(bif_[r]));
                float g_ = tanhf_(lo32(bgo_[r])), o_ = sigf(hi32(bgo_[r]));
                c1[r]  = f_ * c1[r] + i_ * g_;
                h1n[r] = o_ * tanhf_(c1[r]);
            }
            *(float4*)&h1d[j * HP + ro]     = make_float4(h1n[0], h1n[1], h1n[2], h1n[3]);
            *(float4*)&h1d[j * HP + ro + 4] = make_float4(h1n[4], h1n[5], h1n[6], h1n[7]);
            #pragma unroll
            for (int r = 0; r < 8; r++) gx[r] = gxn[r];
        }
        __syncthreads();   // BAR4: new h1 visible; scratch free for next step
    }

    // ---------------- fc (64 -> 5) + softmax on final h1 ----------------
    if (tid < 16) {
        const int row = tid;
        const int b   = base + row;
        float lgt[5];
        float mx = -1e30f;
        #pragma unroll
        for (int o = 0; o < 5; o++) {
            float s = bfc[o];
            #pragma unroll 8
            for (int k = 0; k < 64; k++)
                s += h1d[k * HP + row] * Wfc[o * 64 + k];
            lgt[o] = s;
            mx = fmaxf(mx, s);
        }
        float e[5], den = 0.0f;
        #pragma unroll
        for (int o = 0; o < 5; o++) { e[o] = __expf(lgt[o] - mx); den += e[o]; }
        float inv = __fdividef(1.0f, den);
        #pragma unroll
        for (int o = 0; o < 5; o++) out[(size_t)b * 5 + o] = e[o] * inv;
    }
}

// ============================================================================
extern "C" void kernel_launch(void* const* d_in, const int* in_sizes, int n_in,
                              void* d_out, int out_size)
{
    const float* x    = (const float*)d_in[0];
    const float* Wih0 = (const float*)d_in[1];
    const float* Whh0 = (const float*)d_in[2];
    const float* bih0 = (const float*)d_in[3];
    const float* bhh0 = (const float*)d_in[4];
    const float* Wih1 = (const float*)d_in[5];
    const float* Whh1 = (const float*)d_in[6];
    const float* bih1 = (const float*)d_in[7];
    const float* bhh1 = (const float*)d_in[8];
    const float* Wfc  = (const float*)d_in[9];
    const float* bfc  = (const float*)d_in[10];
    float* out = (float*)d_out;

    cudaFuncSetAttribute(gx0_prepass, cudaFuncAttributeMaxDynamicSharedMemorySize, PP_SMEM);
    cudaFuncSetAttribute(lstm_rec,    cudaFuncAttributeMaxDynamicSharedMemorySize, SMEM_REC);

    gx0_prepass<<<(B_ * T_) / 32, 256, PP_SMEM>>>(x, Wih0, bih0, bhh0);
    lstm_rec<<<B_ / 16, 256, SMEM_REC>>>(Whh0, Wih1, Whh1, bih1, bhh1, Wfc, bfc, out);
}